// round 13
// baseline (speedup 1.0000x reference)
#include <cuda_runtime.h>
#include <cuda_bf16.h>
#include <cstdint>

#define NPTS 100000
#define KC   1024
#define NPAD 100352            // 98 * 1024
#define R2   0.04f

typedef unsigned long long ull;

// ---------------- scratch (static __device__, no allocation) ----------------
__device__ float g_P[NPTS * 64];     // per-point layer-1 partials
__device__ float g_ct[KC * 64];      // per-centroid layer-1 term
__device__ int   g_idx[KC * KC];     // selected neighbor indices (order-free)
__device__ int   g_cnt[KC];          // valid neighbor counts
__device__ uint4 g_Wimg[3072];       // swizzled bf16 weight images
__device__ float4 g_pts[NPAD];       // packed (x,y,z,||p||^2), padded sentinels
__device__ float4 g_cq[KC];          // centroid (x,y,z,||c||^2)
__device__ int   g_cellcnt[4096];    // 16^3 cell histogram
__device__ int   g_cellfill[4096];
__device__ int   g_cellbase[4097];
__device__ float4 g_binpts[NPTS];    // spatially binned points (bit-copies)
__device__ int   g_binid[NPTS];      // original index per binned point

// ---------------- helpers ----------------
__device__ __forceinline__ ull pack2(float lo, float hi) {
    ull r; asm("mov.b64 %0, {%1, %2};" : "=l"(r) : "f"(lo), "f"(hi)); return r;
}
__device__ __forceinline__ ull fma2(ull a, ull b, ull c) {
    ull d; asm("fma.rn.f32x2 %0, %1, %2, %3;" : "=l"(d) : "l"(a), "l"(b), "l"(c)); return d;
}
__device__ __forceinline__ uint32_t smem_u32(const void* p) {
    uint32_t a;
    asm("{ .reg .u64 t; cvta.to.shared.u64 t, %1; cvt.u32.u64 %0, t; }" : "=r"(a) : "l"(p));
    return a;
}
__host__ __device__ __forceinline__ uint32_t swz128(uint32_t b) { return b ^ ((b >> 3) & 0x70); }

// exact fp32 squared distance — same op sequence as the R11 packed version
// (FMUL, FFMA, FFMA, FADD, FFMA), guarded intrinsics so fast-math can't touch it.
__device__ __forceinline__ float d2f(float4 c, float4 p) {
    float dot = __fmul_rn(c.x, p.x);
    dot = __fmaf_rn(c.y, p.y, dot);
    dot = __fmaf_rn(c.z, p.z, dot);
    float s = __fadd_rn(c.w, p.w);
    return __fmaf_rn(dot, -2.0f, s);
}

// bf16 hi/lo split of a float pair, packed as bf16x2 words
__device__ __forceinline__ void split2(float a, float b, uint32_t& hi, uint32_t& lo) {
    __nv_bfloat162 h = __floats2bfloat162_rn(a, b);
    float ra = a - __bfloat162float(h.x);
    float rb = b - __bfloat162float(h.y);
    __nv_bfloat162 l = __floats2bfloat162_rn(ra, rb);
    hi = *reinterpret_cast<uint32_t*>(&h);
    lo = *reinterpret_cast<uint32_t*>(&l);
}

// ---------------- legacy tensor-core primitives (sm_80+, valid on sm_103) ----
__device__ __forceinline__ void ldsm4(uint32_t* r, uint32_t addr) {
    asm volatile("ldmatrix.sync.aligned.m8n8.x4.shared.b16 {%0,%1,%2,%3}, [%4];"
                 : "=r"(r[0]), "=r"(r[1]), "=r"(r[2]), "=r"(r[3]) : "r"(addr));
}
__device__ __forceinline__ void mma_bf16(float* d, const uint32_t* a, const uint32_t* b) {
    asm volatile("mma.sync.aligned.m16n8k16.row.col.f32.bf16.bf16.f32 "
                 "{%0,%1,%2,%3}, {%4,%5,%6,%7}, {%8,%9}, {%0,%1,%2,%3};"
                 : "+f"(d[0]), "+f"(d[1]), "+f"(d[2]), "+f"(d[3])
                 : "r"(a[0]), "r"(a[1]), "r"(a[2]), "r"(a[3]), "r"(b[0]), "r"(b[1]));
}

// ======================================================================
// Stage A0: pack coords + squared norm, padded with far sentinels
// ======================================================================
__global__ __launch_bounds__(256) void k_pack(const float* __restrict__ coords)
{
    int i = blockIdx.x * 256 + threadIdx.x;
    if (i >= NPAD) return;
    float4 v;
    if (i < NPTS) {
        float x = coords[3 * i], y = coords[3 * i + 1], z = coords[3 * i + 2];
        v = make_float4(x, y, z, x * x + y * y + z * z);
    } else {
        v = make_float4(1e9f, 1e9f, 1e9f, 1e9f);
    }
    g_pts[i] = v;
}

// ======================================================================
// Spatial binning: zero -> cell histogram -> prefix -> scatter
// ======================================================================
__device__ __forceinline__ int cell_of(float4 p) {
    int cx = min(15, max(0, (int)(p.x * 16.f)));
    int cy = min(15, max(0, (int)(p.y * 16.f)));
    int cz = min(15, max(0, (int)(p.z * 16.f)));
    return (cz * 16 + cy) * 16 + cx;
}

__global__ __launch_bounds__(256) void k_cellprep()
{
    int i = blockIdx.x * 256 + threadIdx.x;
    if (i < 4096) { g_cellcnt[i] = 0; g_cellfill[i] = 0; }
}

__global__ __launch_bounds__(256) void k_cellcnt()
{
    int i = blockIdx.x * 256 + threadIdx.x;
    if (i >= NPTS) return;
    atomicAdd(&g_cellcnt[cell_of(g_pts[i])], 1);
}

__global__ __launch_bounds__(1024) void k_cellscan()
{
    __shared__ int s[1024];
    const int t = threadIdx.x;
    int v0 = g_cellcnt[4 * t], v1 = g_cellcnt[4 * t + 1];
    int v2 = g_cellcnt[4 * t + 2], v3 = g_cellcnt[4 * t + 3];
    int sum = v0 + v1 + v2 + v3;
    s[t] = sum;
    __syncthreads();
    for (int off = 1; off < 1024; off <<= 1) {
        int x = (t >= off) ? s[t - off] : 0;
        __syncthreads();
        s[t] += x;
        __syncthreads();
    }
    int excl = s[t] - sum;
    g_cellbase[4 * t] = excl;
    g_cellbase[4 * t + 1] = excl + v0;
    g_cellbase[4 * t + 2] = excl + v0 + v1;
    g_cellbase[4 * t + 3] = excl + v0 + v1 + v2;
    if (t == 1023) g_cellbase[4096] = excl + sum;
}

__global__ __launch_bounds__(256) void k_scatter()
{
    int i = blockIdx.x * 256 + threadIdx.x;
    if (i >= NPTS) return;
    float4 p = g_pts[i];
    int c = cell_of(p);
    int pos = g_cellbase[c] + atomicAdd(&g_cellfill[c], 1);
    g_binpts[pos] = p;
    g_binid[pos] = i;
}

// ======================================================================
// Stage A: P[j,:] = coords[j] @ W1[0:3,:] + feats[j] @ W1[3:67,:]  (fp32)
// ======================================================================
__global__ __launch_bounds__(256) void k_P(const float* __restrict__ coords,
                                           const float* __restrict__ feats,
                                           const float* __restrict__ W1)
{
    __shared__ float W1s[67 * 64];
    __shared__ float xs[64 * 68];

    const int tid = threadIdx.x;
    const int row0 = blockIdx.x * 64;

    for (int i = tid; i < 67 * 64; i += 256) W1s[i] = W1[i];
    for (int i = tid; i < 64 * 64; i += 256) {
        int r = i >> 6, c = i & 63; int row = row0 + r;
        xs[r * 68 + 3 + c] = (row < NPTS) ? feats[row * 64 + c] : 0.f;
    }
    for (int i = tid; i < 192; i += 256) {
        int r = i / 3, d = i - 3 * r; int row = row0 + r;
        xs[r * 68 + d] = (row < NPTS) ? coords[row * 3 + d] : 0.f;
    }
    __syncthreads();

    const int r = tid >> 2, seg = tid & 3;
    const int row = row0 + r;
    ull acc[8];
    ull z = pack2(0.f, 0.f);
#pragma unroll
    for (int j = 0; j < 8; j++) acc[j] = z;

    const float* xr = &xs[r * 68];
    for (int k = 0; k < 67; k++) {
        float a = xr[k];
        ull A = pack2(a, a);
        const ull* wr = (const ull*)&W1s[k * 64 + seg * 16];
#pragma unroll
        for (int j = 0; j < 8; j++) acc[j] = fma2(A, wr[j], acc[j]);
    }
    if (row < NPTS) {
        ull* dst = (ull*)&g_P[row * 64 + seg * 16];
#pragma unroll
        for (int j = 0; j < 8; j++) dst[j] = acc[j];
    }
}

// ======================================================================
// Stage B1: centroid coords + ||c||^2 pack + per-centroid layer-1 term
// ======================================================================
__global__ __launch_bounds__(256) void k_cent(const float* __restrict__ coords,
                                              const int* __restrict__ cidx,
                                              const float* __restrict__ W1,
                                              const float* __restrict__ b1,
                                              float* __restrict__ out)
{
    int gid = blockIdx.x * 256 + threadIdx.x;
    if (gid >= KC * 64) return;
    int k = gid >> 6, c = gid & 63;
    int ci = cidx[k];
    float cx = coords[ci * 3 + 0];
    float cy = coords[ci * 3 + 1];
    float cz = coords[ci * 3 + 2];
    g_ct[gid] = b1[c] - (cx * W1[c] + cy * W1[64 + c] + cz * W1[128 + c]);
    if (c < 3) out[k * 3 + c] = coords[ci * 3 + c];
    if (c == 0) g_cq[k] = make_float4(cx, cy, cz, cx * cx + cy * cy + cz * cz);
}

// ======================================================================
// Stage B2: weight prep — [n rows][k=64 bf16] hi/lo images (unchanged)
// ======================================================================
__global__ __launch_bounds__(512) void k_prepW(const float* __restrict__ W2,
                                               const float* __restrict__ W3)
{
    const int tid = threadIdx.x;
    if (tid < 512) {
        int c = tid;
        int n = c >> 3, kc = c & 7;
        uint32_t hi[4], lo[4];
#pragma unroll
        for (int q = 0; q < 4; q++) {
            int k0 = kc * 8 + 2 * q;
            split2(W2[k0 * 64 + n], W2[(k0 + 1) * 64 + n], hi[q], lo[q]);
        }
        int dst = swz128(n * 128 + kc * 16) >> 4;
        g_Wimg[dst]       = make_uint4(hi[0], hi[1], hi[2], hi[3]);
        g_Wimg[512 + dst] = make_uint4(lo[0], lo[1], lo[2], lo[3]);
    }
    for (int c = tid; c < 1024; c += 512) {
        int n = c >> 3, kc = c & 7;
        uint32_t hi[4], lo[4];
#pragma unroll
        for (int q = 0; q < 4; q++) {
            int k0 = kc * 8 + 2 * q;
            split2(W3[k0 * 128 + n], W3[(k0 + 1) * 128 + n], hi[q], lo[q]);
        }
        int dst = swz128(n * 128 + kc * 16) >> 4;
        g_Wimg[1024 + dst] = make_uint4(hi[0], hi[1], hi[2], hi[3]);
        g_Wimg[2048 + dst] = make_uint4(lo[0], lo[1], lo[2], lo[3]);
    }
}

// ======================================================================
// Ball query via spatial pruning. One WARP per centroid (4 warps/block).
// pass1: candidate cells -> smem histogram of hits over idx>>10 buckets.
// cutoff: warp-scan histogram -> bucket B + rank r -> exact ordered
//         ballot scan of g_pts over bucket B -> threshold index T.
// pass2: candidate cells -> append hits with idx <= T (warp-owned offset).
// Selection set == first min(1024, total) hits in index order. Order-free.
// ======================================================================
__global__ __launch_bounds__(128) void k_ball2()
{
    __shared__ int hist[4][128];
    const int w = threadIdx.x >> 5, l = threadIdx.x & 31;
    const int cid = blockIdx.x * 4 + w;

    const float4 c4 = g_cq[cid];
    const int xs0 = max(0,  (int)floorf((c4.x - 0.2002f) * 16.f));
    const int xs1 = min(15, (int)floorf((c4.x + 0.2002f) * 16.f));
    const int ys0 = max(0,  (int)floorf((c4.y - 0.2002f) * 16.f));
    const int ys1 = min(15, (int)floorf((c4.y + 0.2002f) * 16.f));
    const int zs0 = max(0,  (int)floorf((c4.z - 0.2002f) * 16.f));
    const int zs1 = min(15, (int)floorf((c4.z + 0.2002f) * 16.f));

    for (int i = l; i < 128; i += 32) hist[w][i] = 0;
    __syncwarp();

    // ---- pass 1: histogram of hit indices (idx >> 10) ----
    for (int cz = zs0; cz <= zs1; cz++)
        for (int cy = ys0; cy <= ys1; cy++) {
            int row = (cz * 16 + cy) * 16;
            int i0 = g_cellbase[row + xs0];
            int i1 = g_cellbase[row + xs1 + 1];
            for (int i = i0 + l; i < i1; i += 32) {
                float4 p = g_binpts[i];
                if (d2f(c4, p) <= R2)
                    atomicAdd(&hist[w][g_binid[i] >> 10], 1);
            }
        }
    __syncwarp();

    // ---- cutoff: warp scan over 128 buckets (4 chunks of 32) ----
    int h[4], incl[4];
    int C = 0;
#pragma unroll
    for (int j = 0; j < 4; j++) {
        h[j] = hist[w][j * 32 + l];
        int p = h[j];
#pragma unroll
        for (int o = 1; o < 32; o <<= 1) {
            int x = __shfl_up_sync(0xffffffffu, p, o);
            if (l >= o) p += x;
        }
        incl[j] = C + p;
        C += __shfl_sync(0xffffffffu, p, 31);
    }
    const int total = C;

    int T, cnt;
    if (total >= KC) {
        // min bucket with incl >= KC, carry its exclusive prefix
        int bb = 0x7fffffff, ex = 0;
#pragma unroll
        for (int j = 0; j < 4; j++) {
            if (incl[j] >= KC) {
                int b = j * 32 + l;
                if (b < bb) { bb = b; ex = incl[j] - h[j]; }
            }
        }
#pragma unroll
        for (int o = 16; o; o >>= 1) {
            int ob = __shfl_xor_sync(0xffffffffu, bb, o);
            int oe = __shfl_xor_sync(0xffffffffu, ex, o);
            if (ob < bb) { bb = ob; ex = oe; }
        }
        const int r = KC - ex;           // 1-based rank within bucket bb
        const int start = bb << 10;
        int running = 0;
        T = NPTS;
        for (int it = 0; it < 32; it++) {
            float4 p = g_pts[start + it * 32 + l];
            unsigned bal = __ballot_sync(0xffffffffu, d2f(c4, p) <= R2);
            int c = __popc(bal);
            if (running + c >= r) {                      // warp-uniform
                T = start + it * 32 + __fns(bal, 0, r - running);
                break;
            }
            running += c;
        }
        cnt = KC;
    } else {
        T = 0x7fffffff;
        cnt = total;
    }
    if (l == 0) g_cnt[cid] = cnt;

    // ---- pass 2: append hits with idx <= T (uniform trip counts) ----
    int run = 0;
    for (int cz = zs0; cz <= zs1; cz++)
        for (int cy = ys0; cy <= ys1; cy++) {
            int row = (cz * 16 + cy) * 16;
            int i0 = g_cellbase[row + xs0];
            int i1 = g_cellbase[row + xs1 + 1];
            for (int base = i0; base < i1; base += 32) {
                int i = base + l;
                bool pred = false;
                int id = 0;
                if (i < i1) {
                    float4 p = g_binpts[i];
                    id = g_binid[i];
                    pred = (d2f(c4, p) <= R2) && (id <= T);
                }
                unsigned bal = __ballot_sync(0xffffffffu, pred);
                if (pred)
                    g_idx[cid * KC + run + __popc(bal & ((1u << l) - 1u))] = id;
                run += __popc(bal);
            }
        }
}

// ======================================================================
// Stage D: per-centroid MLP via mma.sync bf16 hi/lo split (unchanged)
// ======================================================================
#define SM_AH  0
#define SM_AL  16384
#define SM_W   32768
#define SM_CT  81920
#define SM_B2  82176
#define SM_B3  82432
#define SM_RED 82944
#define SM_TOTAL 87040

__global__ void __launch_bounds__(512, 1)
k_mlp(const float* __restrict__ b2g, const float* __restrict__ b3g,
      float* __restrict__ outF)
{
    extern __shared__ char sm[];
    const uint32_t sb = smem_u32(sm);
    const int tid = threadIdx.x, bid = blockIdx.x;
    const int w = tid >> 5, lane = tid & 31;

    {
        uint4* dst = (uint4*)(sm + SM_W);
        for (int i = tid; i < 3072; i += 512) dst[i] = g_Wimg[i];
        if (tid < 64)       ((float*)(sm + SM_CT))[tid] = g_ct[bid * 64 + tid];
        else if (tid < 128) ((float*)(sm + SM_B2))[tid - 64] = b2g[tid - 64];
        else if (tid < 256) ((float*)(sm + SM_B3))[tid - 128] = b3g[tid - 128];
    }
    const int cnt = g_cnt[bid];
    __syncthreads();

    const int gr = tid >> 2, gseg = tid & 3;
    const float* cts = (const float*)(sm + SM_CT);
    const float* b2s = (const float*)(sm + SM_B2);
    const float* b3s = (const float*)(sm + SM_B3);

    const int mrow = (w & 7) * 16;
    const int nc2  = (w >> 3) * 32;
    const int nc3  = (w >> 3) * 64;
    const uint32_t a_row  = mrow + (lane & 15);
    const uint32_t a_half = ((lane >> 4) & 1) * 16;
    const uint32_t b_nrow = (lane & 7) + ((lane >> 4) & 1) * 8;
    const uint32_t b_koff = ((lane >> 3) & 1) * 16;

    float rmax[16];
#pragma unroll
    for (int i = 0; i < 16; i++) rmax[i] = 0.f;

    for (int t = 0; t * 128 < cnt; t++) {
        {
            const int row = t * 128 + gr;
            float x[16];
            if (row < cnt) {
                int j = g_idx[bid * KC + row];
                const float4* Pp = (const float4*)(g_P + j * 64 + gseg * 16);
#pragma unroll
                for (int q = 0; q < 4; q++) {
                    float4 v = __ldg(Pp + q);
                    float4 c = *(const float4*)&cts[gseg * 16 + q * 4];
                    x[q * 4 + 0] = fmaxf(v.x + c.x, 0.f);
                    x[q * 4 + 1] = fmaxf(v.y + c.y, 0.f);
                    x[q * 4 + 2] = fmaxf(v.z + c.z, 0.f);
                    x[q * 4 + 3] = fmaxf(v.w + c.w, 0.f);
                }
            } else {
#pragma unroll
                for (int i = 0; i < 16; i++) x[i] = 0.f;
            }
            uint32_t hi[8], lo[8];
#pragma unroll
            for (int q = 0; q < 8; q++) split2(x[2 * q], x[2 * q + 1], hi[q], lo[q]);
            uint32_t b0 = gr * 128 + gseg * 32;
            uint32_t s0 = swz128(b0), s1 = swz128(b0 + 16);
            *(uint4*)(sm + SM_AH + s0) = make_uint4(hi[0], hi[1], hi[2], hi[3]);
            *(uint4*)(sm + SM_AH + s1) = make_uint4(hi[4], hi[5], hi[6], hi[7]);
            *(uint4*)(sm + SM_AL + s0) = make_uint4(lo[0], lo[1], lo[2], lo[3]);
            *(uint4*)(sm + SM_AL + s1) = make_uint4(lo[4], lo[5], lo[6], lo[7]);
        }
        __syncthreads();

        uint32_t Ah[4][4], Al[4][4];
#pragma unroll
        for (int kt = 0; kt < 4; kt++) {
            uint32_t off = swz128(a_row * 128 + kt * 32 + a_half);
            ldsm4(Ah[kt], sb + SM_AH + off);
            ldsm4(Al[kt], sb + SM_AL + off);
        }
        __syncthreads();

        float D[4][4];
#pragma unroll
        for (int i = 0; i < 4; i++)
#pragma unroll
            for (int j = 0; j < 4; j++) D[i][j] = 0.f;
#pragma unroll
        for (int p = 0; p < 2; p++) {
#pragma unroll
            for (int kt = 0; kt < 4; kt++) {
                uint32_t off = swz128((nc2 + p * 16 + b_nrow) * 128 + kt * 32 + b_koff);
                uint32_t Bh[4], Bl[4];
                ldsm4(Bh, sb + SM_W + off);
                ldsm4(Bl, sb + SM_W + 8192 + off);
                mma_bf16(D[p * 2 + 0], Ah[kt], Bh + 0);
                mma_bf16(D[p * 2 + 0], Al[kt], Bh + 0);
                mma_bf16(D[p * 2 + 0], Ah[kt], Bl + 0);
                mma_bf16(D[p * 2 + 1], Ah[kt], Bh + 2);
                mma_bf16(D[p * 2 + 1], Al[kt], Bh + 2);
                mma_bf16(D[p * 2 + 1], Ah[kt], Bl + 2);
            }
        }

        {
            const int r0 = mrow + (lane >> 2);
            const int jc = (lane & 3) * 2;
#pragma unroll
            for (int nt = 0; nt < 4; nt++) {
                int j0 = nc2 + nt * 8 + jc;
                float v0 = fmaxf(D[nt][0] + b2s[j0],     0.f);
                float v1 = fmaxf(D[nt][1] + b2s[j0 + 1], 0.f);
                float v2 = fmaxf(D[nt][2] + b2s[j0],     0.f);
                float v3 = fmaxf(D[nt][3] + b2s[j0 + 1], 0.f);
                uint32_t h0, l0, h1, l1;
                split2(v0, v1, h0, l0);
                split2(v2, v3, h1, l1);
                uint32_t o0 = swz128(r0 * 128 + j0 * 2);
                uint32_t o1 = swz128((r0 + 8) * 128 + j0 * 2);
                *(uint32_t*)(sm + SM_AH + o0) = h0;
                *(uint32_t*)(sm + SM_AL + o0) = l0;
                *(uint32_t*)(sm + SM_AH + o1) = h1;
                *(uint32_t*)(sm + SM_AL + o1) = l1;
            }
        }
        __syncthreads();

#pragma unroll
        for (int kt = 0; kt < 4; kt++) {
            uint32_t off = swz128(a_row * 128 + kt * 32 + a_half);
            ldsm4(Ah[kt], sb + SM_AH + off);
            ldsm4(Al[kt], sb + SM_AL + off);
        }
        __syncthreads();

        const int r0g = t * 128 + mrow + (lane >> 2);
        const bool vr0 = (r0g < cnt), vr1 = (r0g + 8 < cnt);
#pragma unroll
        for (int hh = 0; hh < 2; hh++) {
            float D3[4][4];
#pragma unroll
            for (int i = 0; i < 4; i++)
#pragma unroll
                for (int j = 0; j < 4; j++) D3[i][j] = 0.f;
#pragma unroll
            for (int p = 0; p < 2; p++) {
#pragma unroll
                for (int kt = 0; kt < 4; kt++) {
                    uint32_t off = swz128((nc3 + hh * 32 + p * 16 + b_nrow) * 128 + kt * 32 + b_koff);
                    uint32_t Bh[4], Bl[4];
                    ldsm4(Bh, sb + SM_W + 16384 + off);
                    ldsm4(Bl, sb + SM_W + 32768 + off);
                    mma_bf16(D3[p * 2 + 0], Ah[kt], Bh + 0);
                    mma_bf16(D3[p * 2 + 0], Al[kt], Bh + 0);
                    mma_bf16(D3[p * 2 + 0], Ah[kt], Bl + 0);
                    mma_bf16(D3[p * 2 + 1], Ah[kt], Bh + 2);
                    mma_bf16(D3[p * 2 + 1], Al[kt], Bh + 2);
                    mma_bf16(D3[p * 2 + 1], Ah[kt], Bl + 2);
                }
            }
            const int jc = (lane & 3) * 2;
#pragma unroll
            for (int nt = 0; nt < 4; nt++) {
                int j0 = nc3 + hh * 32 + nt * 8 + jc;
                int ri = hh * 8 + nt * 2;
                if (vr0) {
                    rmax[ri]     = fmaxf(rmax[ri],     fmaxf(D3[nt][0] + b3s[j0],     0.f));
                    rmax[ri + 1] = fmaxf(rmax[ri + 1], fmaxf(D3[nt][1] + b3s[j0 + 1], 0.f));
                }
                if (vr1) {
                    rmax[ri]     = fmaxf(rmax[ri],     fmaxf(D3[nt][2] + b3s[j0],     0.f));
                    rmax[ri + 1] = fmaxf(rmax[ri + 1], fmaxf(D3[nt][3] + b3s[j0 + 1], 0.f));
                }
            }
        }
    }

#pragma unroll
    for (int o = 4; o <= 16; o <<= 1)
#pragma unroll
        for (int i = 0; i < 16; i++)
            rmax[i] = fmaxf(rmax[i], __shfl_xor_sync(0xffffffffu, rmax[i], o));
    if (lane < 4) {
        float* red = (float*)(sm + SM_RED);
#pragma unroll
        for (int i = 0; i < 16; i++) {
            int col = nc3 + (i >> 1) * 8 + lane * 2 + (i & 1);
            red[(w & 7) * 128 + col] = rmax[i];
        }
    }
    __syncthreads();
    if (tid < 128) {
        const float* red = (const float*)(sm + SM_RED);
        float m = red[tid];
#pragma unroll
        for (int r = 1; r < 8; r++) m = fmaxf(m, red[r * 128 + tid]);
        outF[bid * 128 + tid] = m;
    }
}

// ======================================================================
extern "C" void kernel_launch(void* const* d_in, const int* in_sizes, int n_in,
                              void* d_out, int out_size)
{
    const float* coords = (const float*)d_in[0];
    const float* feats  = (const float*)d_in[1];
    const int*   cidx   = (const int*)  d_in[2];
    const float* W1 = (const float*)d_in[3];
    const float* b1 = (const float*)d_in[4];
    const float* W2 = (const float*)d_in[5];
    const float* b2 = (const float*)d_in[6];
    const float* W3 = (const float*)d_in[7];
    const float* b3 = (const float*)d_in[8];
    float* out = (float*)d_out;

    cudaFuncSetAttribute((const void*)k_mlp,
                         cudaFuncAttributeMaxDynamicSharedMemorySize, SM_TOTAL);

    k_pack    <<<(NPAD + 255) / 256, 256>>>(coords);
    k_cellprep<<<16, 256>>>();
    k_cellcnt <<<(NPTS + 255) / 256, 256>>>();
    k_cellscan<<<1, 1024>>>();
    k_scatter <<<(NPTS + 255) / 256, 256>>>();
    k_P       <<<(NPTS + 63) / 64, 256>>>(coords, feats, W1);
    k_cent    <<<(KC * 64) / 256, 256>>>(coords, cidx, W1, b1, out);
    k_prepW   <<<1, 512>>>(W2, W3);
    k_ball2   <<<KC / 4, 128>>>();
    k_mlp     <<<KC, 512, SM_TOTAL>>>(b2, b3, out + KC * 3);
}

// round 15
// speedup vs baseline: 1.3668x; 1.3668x over previous
#include <cuda_runtime.h>
#include <cuda_bf16.h>
#include <cstdint>

#define NPTS 100000
#define KC   1024
#define NPAD 100352            // 392 * 256
#define R2   0.04f

typedef unsigned long long ull;

// ---------------- scratch (static __device__, no allocation) ----------------
__device__ float g_P[NPTS * 64];     // per-point layer-1 partials
__device__ float g_ct[KC * 64];      // per-centroid layer-1 term
__device__ int   g_idx[KC * KC];     // selected neighbor indices (order-free)
__device__ int   g_cnt[KC];          // valid neighbor counts
__device__ uint4 g_Wimg[3072];       // swizzled bf16 weight images
__device__ float4 g_pts[NPAD];       // packed (x,y,z,||p||^2), padded sentinels
__device__ float4 g_cq[KC];          // centroid (x,y,z,||c||^2)
__device__ int   g_cellcnt[4096];    // 16^3 cell histogram (self-zeroing cycle)
__device__ int   g_cellfill[4096];   // scatter cursors  (self-zeroing cycle)
__device__ int   g_cellbase[4097];
__device__ float4 g_binpts[NPTS];    // spatially binned points (bit-copies)
__device__ int   g_binid[NPTS];      // original index per binned point

// ---------------- helpers ----------------
__device__ __forceinline__ ull pack2(float lo, float hi) {
    ull r; asm("mov.b64 %0, {%1, %2};" : "=l"(r) : "f"(lo), "f"(hi)); return r;
}
__device__ __forceinline__ ull fma2(ull a, ull b, ull c) {
    ull d; asm("fma.rn.f32x2 %0, %1, %2, %3;" : "=l"(d) : "l"(a), "l"(b), "l"(c)); return d;
}
__device__ __forceinline__ uint32_t smem_u32(const void* p) {
    uint32_t a;
    asm("{ .reg .u64 t; cvta.to.shared.u64 t, %1; cvt.u32.u64 %0, t; }" : "=r"(a) : "l"(p));
    return a;
}
__host__ __device__ __forceinline__ uint32_t swz128(uint32_t b) { return b ^ ((b >> 3) & 0x70); }

// exact fp32 squared distance — identical op sequence everywhere it is used.
__device__ __forceinline__ float d2f(float4 c, float4 p) {
    float dot = __fmul_rn(c.x, p.x);
    dot = __fmaf_rn(c.y, p.y, dot);
    dot = __fmaf_rn(c.z, p.z, dot);
    float s = __fadd_rn(c.w, p.w);
    return __fmaf_rn(dot, -2.0f, s);
}

// bf16 hi/lo split of a float pair, packed as bf16x2 words
__device__ __forceinline__ void split2(float a, float b, uint32_t& hi, uint32_t& lo) {
    __nv_bfloat162 h = __floats2bfloat162_rn(a, b);
    float ra = a - __bfloat162float(h.x);
    float rb = b - __bfloat162float(h.y);
    __nv_bfloat162 l = __floats2bfloat162_rn(ra, rb);
    hi = *reinterpret_cast<uint32_t*>(&h);
    lo = *reinterpret_cast<uint32_t*>(&l);
}

// ---------------- legacy tensor-core primitives (sm_80+, valid on sm_103) ----
__device__ __forceinline__ void ldsm4(uint32_t* r, uint32_t addr) {
    asm volatile("ldmatrix.sync.aligned.m8n8.x4.shared.b16 {%0,%1,%2,%3}, [%4];"
                 : "=r"(r[0]), "=r"(r[1]), "=r"(r[2]), "=r"(r[3]) : "r"(addr));
}
__device__ __forceinline__ void mma_bf16(float* d, const uint32_t* a, const uint32_t* b) {
    asm volatile("mma.sync.aligned.m16n8k16.row.col.f32.bf16.bf16.f32 "
                 "{%0,%1,%2,%3}, {%4,%5,%6,%7}, {%8,%9}, {%0,%1,%2,%3};"
                 : "+f"(d[0]), "+f"(d[1]), "+f"(d[2]), "+f"(d[3])
                 : "r"(a[0]), "r"(a[1]), "r"(a[2]), "r"(a[3]), "r"(b[0]), "r"(b[1]));
}

__device__ __forceinline__ int cell_of(float4 p) {
    int cx = min(15, max(0, (int)(p.x * 16.f)));
    int cy = min(15, max(0, (int)(p.y * 16.f)));
    int cz = min(15, max(0, (int)(p.z * 16.f)));
    return (cz * 16 + cy) * 16 + cx;
}

// ======================================================================
// Launch 1: k_front — fused pack+cellcnt (blocks 0..391) and cent
// (blocks 392..647). g_cellcnt enters zeroed (static init on first call,
// re-zeroed by k_cellscan on every call).
// ======================================================================
__global__ __launch_bounds__(256) void k_front(const float* __restrict__ coords,
                                               const int* __restrict__ cidx,
                                               const float* __restrict__ W1,
                                               const float* __restrict__ b1,
                                               float* __restrict__ out)
{
    const int b = blockIdx.x;
    if (b < 392) {
        int i = b * 256 + threadIdx.x;      // < NPAD
        float4 v;
        if (i < NPTS) {
            float x = coords[3 * i], y = coords[3 * i + 1], z = coords[3 * i + 2];
            v = make_float4(x, y, z, x * x + y * y + z * z);
            atomicAdd(&g_cellcnt[cell_of(v)], 1);
        } else {
            v = make_float4(1e9f, 1e9f, 1e9f, 1e9f);
        }
        g_pts[i] = v;
    } else {
        int gid = (b - 392) * 256 + threadIdx.x;   // < 65536
        int k = gid >> 6, c = gid & 63;
        int ci = cidx[k];
        float cx = coords[ci * 3 + 0];
        float cy = coords[ci * 3 + 1];
        float cz = coords[ci * 3 + 2];
        g_ct[gid] = b1[c] - (cx * W1[c] + cy * W1[64 + c] + cz * W1[128 + c]);
        if (c < 3) out[k * 3 + c] = coords[ci * 3 + c];
        if (c == 0) g_cq[k] = make_float4(cx, cy, cz, cx * cx + cy * cy + cz * cz);
    }
}

// ======================================================================
// Launch 2: prefix over 4096 cell counts; re-zeroes cnt+fill for the
// NEXT launch (self-zeroing cycle keeps kernel_launch deterministic).
// ======================================================================
__global__ __launch_bounds__(1024) void k_cellscan()
{
    __shared__ int s[1024];
    const int t = threadIdx.x;
    int v0 = g_cellcnt[4 * t], v1 = g_cellcnt[4 * t + 1];
    int v2 = g_cellcnt[4 * t + 2], v3 = g_cellcnt[4 * t + 3];
    // re-zero for the next kernel_launch invocation
    g_cellcnt[4 * t] = 0; g_cellcnt[4 * t + 1] = 0;
    g_cellcnt[4 * t + 2] = 0; g_cellcnt[4 * t + 3] = 0;
    g_cellfill[4 * t] = 0; g_cellfill[4 * t + 1] = 0;
    g_cellfill[4 * t + 2] = 0; g_cellfill[4 * t + 3] = 0;
    int sum = v0 + v1 + v2 + v3;
    s[t] = sum;
    __syncthreads();
    for (int off = 1; off < 1024; off <<= 1) {
        int x = (t >= off) ? s[t - off] : 0;
        __syncthreads();
        s[t] += x;
        __syncthreads();
    }
    int excl = s[t] - sum;
    g_cellbase[4 * t] = excl;
    g_cellbase[4 * t + 1] = excl + v0;
    g_cellbase[4 * t + 2] = excl + v0 + v1;
    g_cellbase[4 * t + 3] = excl + v0 + v1 + v2;
    if (t == 1023) g_cellbase[4096] = excl + sum;
}

// ======================================================================
// Launch 3: scatter points into cell-sorted order (keeps original id)
// ======================================================================
__global__ __launch_bounds__(256) void k_scatter()
{
    int i = blockIdx.x * 256 + threadIdx.x;
    if (i >= NPTS) return;
    float4 p = g_pts[i];
    int c = cell_of(p);
    int pos = g_cellbase[c] + atomicAdd(&g_cellfill[c], 1);
    g_binpts[pos] = p;
    g_binid[pos] = i;
}

// ======================================================================
// Launch 4 (PROFILED): ball query, one BLOCK (8 warps) per centroid.
// pass1: candidate cells -> hist[idx>>10] (smem atomics, all 8 warps).
// cutoff: warp 0 scans histogram -> bucket B + rank r -> ordered ballot
//         scan of g_pts over bucket B -> exact threshold index T.
// pass2: candidate cells -> append hits with id <= T via shared atomic
//        allocator (order-free; k_mlp max-pool is permutation-invariant).
// ======================================================================
__global__ __launch_bounds__(256) void k_ball3()
{
    __shared__ int hist[128];
    __shared__ int sT, sCtr;
    const int tid = threadIdx.x, w = tid >> 5, l = tid & 31;
    const int cid = blockIdx.x;

    const float4 c4 = g_cq[cid];
    const int xs0 = max(0,  (int)floorf((c4.x - 0.2002f) * 16.f));
    const int xs1 = min(15, (int)floorf((c4.x + 0.2002f) * 16.f));
    const int ys0 = max(0,  (int)floorf((c4.y - 0.2002f) * 16.f));
    const int ys1 = min(15, (int)floorf((c4.y + 0.2002f) * 16.f));
    const int zs0 = max(0,  (int)floorf((c4.z - 0.2002f) * 16.f));
    const int zs1 = min(15, (int)floorf((c4.z + 0.2002f) * 16.f));
    const int ny = ys1 - ys0 + 1;
    const int nrows = (zs1 - zs0 + 1) * ny;

    for (int i = tid; i < 128; i += 256) hist[i] = 0;
    if (tid == 0) sCtr = 0;
    __syncthreads();

    // ---- pass 1: histogram of hit indices (idx >> 10), warps split rows ----
    for (int rho = w; rho < nrows; rho += 8) {
        int cz = zs0 + rho / ny, cy = ys0 + rho % ny;
        int row = (cz * 16 + cy) * 16;
        int i0 = g_cellbase[row + xs0];
        int i1 = g_cellbase[row + xs1 + 1];
        for (int i = i0 + l; i < i1; i += 32) {
            float4 p = g_binpts[i];
            if (d2f(c4, p) <= R2)
                atomicAdd(&hist[g_binid[i] >> 10], 1);
        }
    }
    __syncthreads();

    // ---- cutoff: warp 0 scans 128 buckets, resolves exact threshold T ----
    if (w == 0) {
        int h[4], incl[4];
        int C = 0;
#pragma unroll
        for (int j = 0; j < 4; j++) {
            h[j] = hist[j * 32 + l];
            int p = h[j];
#pragma unroll
            for (int o = 1; o < 32; o <<= 1) {
                int x = __shfl_up_sync(0xffffffffu, p, o);
                if (l >= o) p += x;
            }
            incl[j] = C + p;
            C += __shfl_sync(0xffffffffu, p, 31);
        }
        const int total = C;
        int T, cnt;
        if (total >= KC) {
            int bb = 0x7fffffff, ex = 0;
#pragma unroll
            for (int j = 0; j < 4; j++) {
                if (incl[j] >= KC) {
                    int b = j * 32 + l;
                    if (b < bb) { bb = b; ex = incl[j] - h[j]; }
                }
            }
#pragma unroll
            for (int o = 16; o; o >>= 1) {
                int ob = __shfl_xor_sync(0xffffffffu, bb, o);
                int oe = __shfl_xor_sync(0xffffffffu, ex, o);
                if (ob < bb) { bb = ob; ex = oe; }
            }
            const int r = KC - ex;                 // 1-based rank in bucket bb
            const int start = bb << 10;
            int running = 0;
            T = NPTS;
            for (int it = 0; it < 32; it++) {
                float4 p = g_pts[start + it * 32 + l];
                unsigned bal = __ballot_sync(0xffffffffu, d2f(c4, p) <= R2);
                int c = __popc(bal);
                if (running + c >= r) {            // warp-uniform
                    T = start + it * 32 + __fns(bal, 0, r - running);
                    break;
                }
                running += c;
            }
            cnt = KC;
        } else {
            T = 0x7fffffff;
            cnt = total;
        }
        if (l == 0) { sT = T; g_cnt[cid] = cnt; }
    }
    __syncthreads();
    const int T = sT;

    // ---- pass 2: append hits with id <= T (uniform chunk loops) ----
    for (int rho = w; rho < nrows; rho += 8) {
        int cz = zs0 + rho / ny, cy = ys0 + rho % ny;
        int row = (cz * 16 + cy) * 16;
        int i0 = g_cellbase[row + xs0];
        int i1 = g_cellbase[row + xs1 + 1];
        for (int base = i0; base < i1; base += 32) {
            int i = base + l;
            bool pred = false;
            int id = 0;
            if (i < i1) {
                float4 p = g_binpts[i];
                id = g_binid[i];
                pred = (d2f(c4, p) <= R2) && (id <= T);
            }
            unsigned bal = __ballot_sync(0xffffffffu, pred);
            int n = __popc(bal);
            if (n) {
                int basepos;
                if (l == 0) basepos = atomicAdd(&sCtr, n);
                basepos = __shfl_sync(0xffffffffu, basepos, 0);
                if (pred) {
                    int off = basepos + __popc(bal & ((1u << l) - 1u));
                    if (off < KC) g_idx[cid * KC + off] = id;
                }
            }
        }
    }
}

// ======================================================================
// Launch 5: weight prep — [n rows][k=64 bf16] hi/lo images (unchanged)
// ======================================================================
__global__ __launch_bounds__(512) void k_prepW(const float* __restrict__ W2,
                                               const float* __restrict__ W3)
{
    const int tid = threadIdx.x;
    if (tid < 512) {
        int c = tid;
        int n = c >> 3, kc = c & 7;
        uint32_t hi[4], lo[4];
#pragma unroll
        for (int q = 0; q < 4; q++) {
            int k0 = kc * 8 + 2 * q;
            split2(W2[k0 * 64 + n], W2[(k0 + 1) * 64 + n], hi[q], lo[q]);
        }
        int dst = swz128(n * 128 + kc * 16) >> 4;
        g_Wimg[dst]       = make_uint4(hi[0], hi[1], hi[2], hi[3]);
        g_Wimg[512 + dst] = make_uint4(lo[0], lo[1], lo[2], lo[3]);
    }
    for (int c = tid; c < 1024; c += 512) {
        int n = c >> 3, kc = c & 7;
        uint32_t hi[4], lo[4];
#pragma unroll
        for (int q = 0; q < 4; q++) {
            int k0 = kc * 8 + 2 * q;
            split2(W3[k0 * 128 + n], W3[(k0 + 1) * 128 + n], hi[q], lo[q]);
        }
        int dst = swz128(n * 128 + kc * 16) >> 4;
        g_Wimg[1024 + dst] = make_uint4(hi[0], hi[1], hi[2], hi[3]);
        g_Wimg[2048 + dst] = make_uint4(lo[0], lo[1], lo[2], lo[3]);
    }
}

// ======================================================================
// Launch 6: P[j,:] = coords[j] @ W1[0:3,:] + feats[j] @ W1[3:67,:]
// ======================================================================
__global__ __launch_bounds__(256) void k_P(const float* __restrict__ coords,
                                           const float* __restrict__ feats,
                                           const float* __restrict__ W1)
{
    __shared__ float W1s[67 * 64];
    __shared__ float xs[64 * 68];

    const int tid = threadIdx.x;
    const int row0 = blockIdx.x * 64;

    for (int i = tid; i < 67 * 64; i += 256) W1s[i] = W1[i];
    for (int i = tid; i < 64 * 64; i += 256) {
        int r = i >> 6, c = i & 63; int row = row0 + r;
        xs[r * 68 + 3 + c] = (row < NPTS) ? feats[row * 64 + c] : 0.f;
    }
    for (int i = tid; i < 192; i += 256) {
        int r = i / 3, d = i - 3 * r; int row = row0 + r;
        xs[r * 68 + d] = (row < NPTS) ? coords[row * 3 + d] : 0.f;
    }
    __syncthreads();

    const int r = tid >> 2, seg = tid & 3;
    const int row = row0 + r;
    ull acc[8];
    ull z = pack2(0.f, 0.f);
#pragma unroll
    for (int j = 0; j < 8; j++) acc[j] = z;

    const float* xr = &xs[r * 68];
    for (int k = 0; k < 67; k++) {
        float a = xr[k];
        ull A = pack2(a, a);
        const ull* wr = (const ull*)&W1s[k * 64 + seg * 16];
#pragma unroll
        for (int j = 0; j < 8; j++) acc[j] = fma2(A, wr[j], acc[j]);
    }
    if (row < NPTS) {
        ull* dst = (ull*)&g_P[row * 64 + seg * 16];
#pragma unroll
        for (int j = 0; j < 8; j++) dst[j] = acc[j];
    }
}

// ======================================================================
// Launch 7: per-centroid MLP via mma.sync bf16 hi/lo split (unchanged)
// ======================================================================
#define SM_AH  0
#define SM_AL  16384
#define SM_W   32768
#define SM_CT  81920
#define SM_B2  82176
#define SM_B3  82432
#define SM_RED 82944
#define SM_TOTAL 87040

__global__ void __launch_bounds__(512, 1)
k_mlp(const float* __restrict__ b2g, const float* __restrict__ b3g,
      float* __restrict__ outF)
{
    extern __shared__ char sm[];
    const uint32_t sb = smem_u32(sm);
    const int tid = threadIdx.x, bid = blockIdx.x;
    const int w = tid >> 5, lane = tid & 31;

    {
        uint4* dst = (uint4*)(sm + SM_W);
        for (int i = tid; i < 3072; i += 512) dst[i] = g_Wimg[i];
        if (tid < 64)       ((float*)(sm + SM_CT))[tid] = g_ct[bid * 64 + tid];
        else if (tid < 128) ((float*)(sm + SM_B2))[tid - 64] = b2g[tid - 64];
        else if (tid < 256) ((float*)(sm + SM_B3))[tid - 128] = b3g[tid - 128];
    }
    const int cnt = g_cnt[bid];
    __syncthreads();

    const int gr = tid >> 2, gseg = tid & 3;
    const float* cts = (const float*)(sm + SM_CT);
    const float* b2s = (const float*)(sm + SM_B2);
    const float* b3s = (const float*)(sm + SM_B3);

    const int mrow = (w & 7) * 16;
    const int nc2  = (w >> 3) * 32;
    const int nc3  = (w >> 3) * 64;
    const uint32_t a_row  = mrow + (lane & 15);
    const uint32_t a_half = ((lane >> 4) & 1) * 16;
    const uint32_t b_nrow = (lane & 7) + ((lane >> 4) & 1) * 8;
    const uint32_t b_koff = ((lane >> 3) & 1) * 16;

    float rmax[16];
#pragma unroll
    for (int i = 0; i < 16; i++) rmax[i] = 0.f;

    for (int t = 0; t * 128 < cnt; t++) {
        {
            const int row = t * 128 + gr;
            float x[16];
            if (row < cnt) {
                int j = g_idx[bid * KC + row];
                const float4* Pp = (const float4*)(g_P + j * 64 + gseg * 16);
#pragma unroll
                for (int q = 0; q < 4; q++) {
                    float4 v = __ldg(Pp + q);
                    float4 c = *(const float4*)&cts[gseg * 16 + q * 4];
                    x[q * 4 + 0] = fmaxf(v.x + c.x, 0.f);
                    x[q * 4 + 1] = fmaxf(v.y + c.y, 0.f);
                    x[q * 4 + 2] = fmaxf(v.z + c.z, 0.f);
                    x[q * 4 + 3] = fmaxf(v.w + c.w, 0.f);
                }
            } else {
#pragma unroll
                for (int i = 0; i < 16; i++) x[i] = 0.f;
            }
            uint32_t hi[8], lo[8];
#pragma unroll
            for (int q = 0; q < 8; q++) split2(x[2 * q], x[2 * q + 1], hi[q], lo[q]);
            uint32_t b0 = gr * 128 + gseg * 32;
            uint32_t s0 = swz128(b0), s1 = swz128(b0 + 16);
            *(uint4*)(sm + SM_AH + s0) = make_uint4(hi[0], hi[1], hi[2], hi[3]);
            *(uint4*)(sm + SM_AH + s1) = make_uint4(hi[4], hi[5], hi[6], hi[7]);
            *(uint4*)(sm + SM_AL + s0) = make_uint4(lo[0], lo[1], lo[2], lo[3]);
            *(uint4*)(sm + SM_AL + s1) = make_uint4(lo[4], lo[5], lo[6], lo[7]);
        }
        __syncthreads();

        uint32_t Ah[4][4], Al[4][4];
#pragma unroll
        for (int kt = 0; kt < 4; kt++) {
            uint32_t off = swz128(a_row * 128 + kt * 32 + a_half);
            ldsm4(Ah[kt], sb + SM_AH + off);
            ldsm4(Al[kt], sb + SM_AL + off);
        }
        __syncthreads();

        float D[4][4];
#pragma unroll
        for (int i = 0; i < 4; i++)
#pragma unroll
            for (int j = 0; j < 4; j++) D[i][j] = 0.f;
#pragma unroll
        for (int p = 0; p < 2; p++) {
#pragma unroll
            for (int kt = 0; kt < 4; kt++) {
                uint32_t off = swz128((nc2 + p * 16 + b_nrow) * 128 + kt * 32 + b_koff);
                uint32_t Bh[4], Bl[4];
                ldsm4(Bh, sb + SM_W + off);
                ldsm4(Bl, sb + SM_W + 8192 + off);
                mma_bf16(D[p * 2 + 0], Ah[kt], Bh + 0);
                mma_bf16(D[p * 2 + 0], Al[kt], Bh + 0);
                mma_bf16(D[p * 2 + 0], Ah[kt], Bl + 0);
                mma_bf16(D[p * 2 + 1], Ah[kt], Bh + 2);
                mma_bf16(D[p * 2 + 1], Al[kt], Bh + 2);
                mma_bf16(D[p * 2 + 1], Ah[kt], Bl + 2);
            }
        }

        {
            const int r0 = mrow + (lane >> 2);
            const int jc = (lane & 3) * 2;
#pragma unroll
            for (int nt = 0; nt < 4; nt++) {
                int j0 = nc2 + nt * 8 + jc;
                float v0 = fmaxf(D[nt][0] + b2s[j0],     0.f);
                float v1 = fmaxf(D[nt][1] + b2s[j0 + 1], 0.f);
                float v2 = fmaxf(D[nt][2] + b2s[j0],     0.f);
                float v3 = fmaxf(D[nt][3] + b2s[j0 + 1], 0.f);
                uint32_t h0, l0, h1, l1;
                split2(v0, v1, h0, l0);
                split2(v2, v3, h1, l1);
                uint32_t o0 = swz128(r0 * 128 + j0 * 2);
                uint32_t o1 = swz128((r0 + 8) * 128 + j0 * 2);
                *(uint32_t*)(sm + SM_AH + o0) = h0;
                *(uint32_t*)(sm + SM_AL + o0) = l0;
                *(uint32_t*)(sm + SM_AH + o1) = h1;
                *(uint32_t*)(sm + SM_AL + o1) = l1;
            }
        }
        __syncthreads();

#pragma unroll
        for (int kt = 0; kt < 4; kt++) {
            uint32_t off = swz128(a_row * 128 + kt * 32 + a_half);
            ldsm4(Ah[kt], sb + SM_AH + off);
            ldsm4(Al[kt], sb + SM_AL + off);
        }
        __syncthreads();

        const int r0g = t * 128 + mrow + (lane >> 2);
        const bool vr0 = (r0g < cnt), vr1 = (r0g + 8 < cnt);
#pragma unroll
        for (int hh = 0; hh < 2; hh++) {
            float D3[4][4];
#pragma unroll
            for (int i = 0; i < 4; i++)
#pragma unroll
                for (int j = 0; j < 4; j++) D3[i][j] = 0.f;
#pragma unroll
            for (int p = 0; p < 2; p++) {
#pragma unroll
                for (int kt = 0; kt < 4; kt++) {
                    uint32_t off = swz128((nc3 + hh * 32 + p * 16 + b_nrow) * 128 + kt * 32 + b_koff);
                    uint32_t Bh[4], Bl[4];
                    ldsm4(Bh, sb + SM_W + 16384 + off);
                    ldsm4(Bl, sb + SM_W + 32768 + off);
                    mma_bf16(D3[p * 2 + 0], Ah[kt], Bh + 0);
                    mma_bf16(D3[p * 2 + 0], Al[kt], Bh + 0);
                    mma_bf16(D3[p * 2 + 0], Ah[kt], Bl + 0);
                    mma_bf16(D3[p * 2 + 1], Ah[kt], Bh + 2);
                    mma_bf16(D3[p * 2 + 1], Al[kt], Bh + 2);
                    mma_bf16(D3[p * 2 + 1], Ah[kt], Bl + 2);
                }
            }
            const int jc = (lane & 3) * 2;
#pragma unroll
            for (int nt = 0; nt < 4; nt++) {
                int j0 = nc3 + hh * 32 + nt * 8 + jc;
                int ri = hh * 8 + nt * 2;
                if (vr0) {
                    rmax[ri]     = fmaxf(rmax[ri],     fmaxf(D3[nt][0] + b3s[j0],     0.f));
                    rmax[ri + 1] = fmaxf(rmax[ri + 1], fmaxf(D3[nt][1] + b3s[j0 + 1], 0.f));
                }
                if (vr1) {
                    rmax[ri]     = fmaxf(rmax[ri],     fmaxf(D3[nt][2] + b3s[j0],     0.f));
                    rmax[ri + 1] = fmaxf(rmax[ri + 1], fmaxf(D3[nt][3] + b3s[j0 + 1], 0.f));
                }
            }
        }
    }

#pragma unroll
    for (int o = 4; o <= 16; o <<= 1)
#pragma unroll
        for (int i = 0; i < 16; i++)
            rmax[i] = fmaxf(rmax[i], __shfl_xor_sync(0xffffffffu, rmax[i], o));
    if (lane < 4) {
        float* red = (float*)(sm + SM_RED);
#pragma unroll
        for (int i = 0; i < 16; i++) {
            int col = nc3 + (i >> 1) * 8 + lane * 2 + (i & 1);
            red[(w & 7) * 128 + col] = rmax[i];
        }
    }
    __syncthreads();
    if (tid < 128) {
        const float* red = (const float*)(sm + SM_RED);
        float m = red[tid];
#pragma unroll
        for (int r = 1; r < 8; r++) m = fmaxf(m, red[r * 128 + tid]);
        outF[bid * 128 + tid] = m;
    }
}

// ======================================================================
extern "C" void kernel_launch(void* const* d_in, const int* in_sizes, int n_in,
                              void* d_out, int out_size)
{
    const float* coords = (const float*)d_in[0];
    const float* feats  = (const float*)d_in[1];
    const int*   cidx   = (const int*)  d_in[2];
    const float* W1 = (const float*)d_in[3];
    const float* b1 = (const float*)d_in[4];
    const float* W2 = (const float*)d_in[5];
    const float* b2 = (const float*)d_in[6];
    const float* W3 = (const float*)d_in[7];
    const float* b3 = (const float*)d_in[8];
    float* out = (float*)d_out;

    cudaFuncSetAttribute((const void*)k_mlp,
                         cudaFuncAttributeMaxDynamicSharedMemorySize, SM_TOTAL);

    k_front   <<<648, 256>>>(coords, cidx, W1, b1, out);   // 1
    k_cellscan<<<1, 1024>>>();                             // 2
    k_scatter <<<(NPTS + 255) / 256, 256>>>();             // 3
    k_ball3   <<<KC, 256>>>();                             // 4 <- profiled
    k_prepW   <<<1, 512>>>(W2, W3);                        // 5
    k_P       <<<(NPTS + 63) / 64, 256>>>(coords, feats, W1); // 6
    k_mlp     <<<KC, 512, SM_TOTAL>>>(b2, b3, out + KC * 3);  // 7
}